// round 12
// baseline (speedup 1.0000x reference)
#include <cuda_runtime.h>

// BatchNorm over features: X[N, D], stats over axis 0. N=131072, D=512, fp32.
//
// Round 12: fused persistent kernel (296 blocks co-resident, grid barriers)
// + SMEM front-cache. Memory plan per block region (~0.88 MB):
//   phase 1 reads front-to-back; the FIRST C=11 iterations/thread (~88 KB)
//   are also stored into dynamic SMEM. Phase 2 normalizes BACK-TO-FRONT:
//   tail served by L2 (freshest lines, LIFO vs LRU), middle from DRAM,
//   front served entirely from SMEM (no global read at all).
// Chip-wide: ~126 MB from L2 + ~26 MB from SMEM of the 256 MB re-read.

#define NROWS  131072
#define DCOLS  512
#define DV     128                  // DCOLS/4 float4 quads per row
#define GRID   296                  // 2 blocks/SM x 148 SMs
#define NTH    512
#define NCH16  (NROWS / 16)         // 8192 16-row chunks
#define CCH    11                   // SMEM-cached float4 iterations per thread

// Dynamic SMEM layout: [cache: CCH*512 float4][shs: 512 float4][shq: 512 float4]
#define SMEM_BYTES ((CCH + 2) * NTH * 16)

// Scratch (__device__ globals; allocation forbidden).
__device__ float g_psum[DCOLS * GRID];   // [col * GRID + block]
__device__ float g_psq [DCOLS * GRID];
__device__ __align__(16) float g_scale[DCOLS];
__device__ __align__(16) float g_shift[DCOLS];
__device__ unsigned g_bar0;
__device__ unsigned g_bar1;

// Reset barrier state every launch (graph replays need pristine counters).
__global__ void bn_init_kernel() { g_bar0 = 0u; g_bar1 = 0u; }

// Grid-wide barrier: release fence + atomic arrive, acquire-load spin.
// Safe only because all GRID blocks are co-resident (occ 2 x 148 SMs).
__device__ __forceinline__ void grid_barrier(unsigned* ctr, int tid) {
    __syncthreads();
    if (tid == 0) {
        __threadfence();
        atomicAdd(ctr, 1u);
        unsigned v;
        do {
            asm volatile("ld.acquire.gpu.u32 %0, [%1];"
                         : "=r"(v) : "l"(ctr) : "memory");
            if (v >= GRID) break;
            __nanosleep(64);
        } while (true);
    }
    __syncthreads();
}

__global__ __launch_bounds__(NTH, 2)
void bn_fused_kernel(const float4* __restrict__ Xv, float4* __restrict__ Yv,
                     const float* __restrict__ gamma,
                     const float* __restrict__ beta) {
    extern __shared__ float4 smem[];
    float4* xcache = smem;                     // [CCH * NTH]
    float4* shs    = smem + CCH * NTH;         // [NTH]
    float4* shq    = smem + (CCH + 1) * NTH;   // [NTH]

    const int b   = blockIdx.x;
    const int tid = threadIdx.x;
    const int cq  = tid & 127;   // column quad 0..127
    const int lr  = tid >> 7;    // row lane   0..3

    // Contiguous region: chunks [cs, ce) of 16 rows (27 or 28 chunks).
    const int cs = (int)(((long long)b       * NCH16) / GRID);
    const int ce = (int)(((long long)(b + 1) * NCH16) / GRID);
    const int nIter = (ce - cs) * 4;           // float4-rows per thread
    const size_t base = ((size_t)cs * 16 + (size_t)lr) * DV + (size_t)cq;

    // ---------------- Phase 1: reduce front-to-back ----------------
    float sx = 0.f, sy = 0.f, sz = 0.f, sw = 0.f;
    float qx = 0.f, qy = 0.f, qz = 0.f, qw = 0.f;

    // Front portion: accumulate AND stash in SMEM cache.
    #pragma unroll
    for (int i = 0; i < CCH; i++) {
        float4 x = Xv[base + (size_t)i * (4 * DV)];
        xcache[i * NTH + tid] = x;
        sx += x.x; sy += x.y; sz += x.z; sw += x.w;
        qx = fmaf(x.x, x.x, qx); qy = fmaf(x.y, x.y, qy);
        qz = fmaf(x.z, x.z, qz); qw = fmaf(x.w, x.w, qw);
    }

    // Remainder: plain batched stream (peel to multiple of 4 first).
    int i = CCH;
    for (; i + 3 < nIter; i += 4) {
        float4 x0 = Xv[base + (size_t)(i + 0) * (4 * DV)];
        float4 x1 = Xv[base + (size_t)(i + 1) * (4 * DV)];
        float4 x2 = Xv[base + (size_t)(i + 2) * (4 * DV)];
        float4 x3 = Xv[base + (size_t)(i + 3) * (4 * DV)];

        sx += x0.x; sy += x0.y; sz += x0.z; sw += x0.w;
        qx = fmaf(x0.x, x0.x, qx); qy = fmaf(x0.y, x0.y, qy);
        qz = fmaf(x0.z, x0.z, qz); qw = fmaf(x0.w, x0.w, qw);

        sx += x1.x; sy += x1.y; sz += x1.z; sw += x1.w;
        qx = fmaf(x1.x, x1.x, qx); qy = fmaf(x1.y, x1.y, qy);
        qz = fmaf(x1.z, x1.z, qz); qw = fmaf(x1.w, x1.w, qw);

        sx += x2.x; sy += x2.y; sz += x2.z; sw += x2.w;
        qx = fmaf(x2.x, x2.x, qx); qy = fmaf(x2.y, x2.y, qy);
        qz = fmaf(x2.z, x2.z, qz); qw = fmaf(x2.w, x2.w, qw);

        sx += x3.x; sy += x3.y; sz += x3.z; sw += x3.w;
        qx = fmaf(x3.x, x3.x, qx); qy = fmaf(x3.y, x3.y, qy);
        qz = fmaf(x3.z, x3.z, qz); qw = fmaf(x3.w, x3.w, qw);
    }
    for (; i < nIter; i++) {
        float4 x = Xv[base + (size_t)i * (4 * DV)];
        sx += x.x; sy += x.y; sz += x.z; sw += x.w;
        qx = fmaf(x.x, x.x, qx); qy = fmaf(x.y, x.y, qy);
        qz = fmaf(x.z, x.z, qz); qw = fmaf(x.w, x.w, qw);
    }

    // Cross-lane (4 warps' worth) reduction through SMEM.
    shs[tid] = make_float4(sx, sy, sz, sw);
    shq[tid] = make_float4(qx, qy, qz, qw);
    __syncthreads();

    if (lr == 0) {
        float4 s = shs[cq];
        float4 q = shq[cq];
        #pragma unroll
        for (int k = 1; k < 4; k++) {
            float4 a  = shs[cq + 128 * k];
            float4 c2 = shq[cq + 128 * k];
            s.x += a.x; s.y += a.y; s.z += a.z; s.w += a.w;
            q.x += c2.x; q.y += c2.y; q.z += c2.z; q.w += c2.w;
        }
        const int col0 = 4 * cq;
        g_psum[(size_t)(col0 + 0) * GRID + b] = s.x;
        g_psum[(size_t)(col0 + 1) * GRID + b] = s.y;
        g_psum[(size_t)(col0 + 2) * GRID + b] = s.z;
        g_psum[(size_t)(col0 + 3) * GRID + b] = s.w;
        g_psq [(size_t)(col0 + 0) * GRID + b] = q.x;
        g_psq [(size_t)(col0 + 1) * GRID + b] = q.y;
        g_psq [(size_t)(col0 + 2) * GRID + b] = q.z;
        g_psq [(size_t)(col0 + 3) * GRID + b] = q.w;
    }

    // ---------------- Barrier 1: all partials visible ----------------
    grid_barrier(&g_bar0, tid);

    // ---------------- Finalize: block b handles columns b, b+GRID ----------
    {
        __shared__ float ss[16];
        __shared__ float sq[16];
        for (int c = b; c < DCOLS; c += GRID) {
            float s = 0.f, q = 0.f;
            if (tid < GRID) {
                s = g_psum[(size_t)c * GRID + tid];
                q = g_psq [(size_t)c * GRID + tid];
            }
            #pragma unroll
            for (int off = 16; off > 0; off >>= 1) {
                s += __shfl_down_sync(0xFFFFFFFFu, s, off);
                q += __shfl_down_sync(0xFFFFFFFFu, q, off);
            }
            const int warp = tid >> 5;
            const int lane = tid & 31;
            if (lane == 0) { ss[warp] = s; sq[warp] = q; }
            __syncthreads();
            if (tid < 16) {
                s = ss[tid];
                q = sq[tid];
                #pragma unroll
                for (int off = 8; off > 0; off >>= 1) {
                    s += __shfl_down_sync(0x0000FFFFu, s, off);
                    q += __shfl_down_sync(0x0000FFFFu, q, off);
                }
                if (tid == 0) {
                    const float inv_n = 1.0f / (float)NROWS;
                    float mean = s * inv_n;
                    float var  = fmaf(-mean, mean, q * inv_n);
                    float inv  = rsqrtf(var);       // no epsilon (matches reference)
                    float scv  = inv * gamma[c];
                    g_scale[c] = scv;
                    g_shift[c] = fmaf(-mean, scv, beta[c]);
                }
            }
            __syncthreads();
        }
    }

    // ---------------- Barrier 2: scale/shift visible ----------------
    grid_barrier(&g_bar1, tid);

    const float4 sc = reinterpret_cast<const float4*>(g_scale)[cq];
    const float4 sh = reinterpret_cast<const float4*>(g_shift)[cq];

    // ---------------- Phase 2: normalize BACK-TO-FRONT ----------------
    // Tail from L2 (freshest), middle from DRAM, front from SMEM cache.
    int j = nIter;
    for (; j - 4 >= CCH; j -= 4) {
        const size_t i0 = base + (size_t)(j - 4) * (4 * DV);
        const size_t i1 = base + (size_t)(j - 3) * (4 * DV);
        const size_t i2 = base + (size_t)(j - 2) * (4 * DV);
        const size_t i3 = base + (size_t)(j - 1) * (4 * DV);
        float4 x0 = Xv[i0];
        float4 x1 = Xv[i1];
        float4 x2 = Xv[i2];
        float4 x3 = Xv[i3];
        float4 y;
        y.x = fmaf(x3.x, sc.x, sh.x); y.y = fmaf(x3.y, sc.y, sh.y);
        y.z = fmaf(x3.z, sc.z, sh.z); y.w = fmaf(x3.w, sc.w, sh.w);
        __stcs(&Yv[i3], y);
        y.x = fmaf(x2.x, sc.x, sh.x); y.y = fmaf(x2.y, sc.y, sh.y);
        y.z = fmaf(x2.z, sc.z, sh.z); y.w = fmaf(x2.w, sc.w, sh.w);
        __stcs(&Yv[i2], y);
        y.x = fmaf(x1.x, sc.x, sh.x); y.y = fmaf(x1.y, sc.y, sh.y);
        y.z = fmaf(x1.z, sc.z, sh.z); y.w = fmaf(x1.w, sc.w, sh.w);
        __stcs(&Yv[i1], y);
        y.x = fmaf(x0.x, sc.x, sh.x); y.y = fmaf(x0.y, sc.y, sh.y);
        y.z = fmaf(x0.z, sc.z, sh.z); y.w = fmaf(x0.w, sc.w, sh.w);
        __stcs(&Yv[i0], y);
    }
    for (; j > CCH; j--) {
        const size_t idx = base + (size_t)(j - 1) * (4 * DV);
        float4 x = Xv[idx];
        float4 y;
        y.x = fmaf(x.x, sc.x, sh.x); y.y = fmaf(x.y, sc.y, sh.y);
        y.z = fmaf(x.z, sc.z, sh.z); y.w = fmaf(x.w, sc.w, sh.w);
        __stcs(&Yv[idx], y);
    }
    // Front portion: served entirely from SMEM — zero global reads.
    #pragma unroll
    for (int k = CCH - 1; k >= 0; k--) {
        float4 x = xcache[k * NTH + tid];
        float4 y;
        y.x = fmaf(x.x, sc.x, sh.x); y.y = fmaf(x.y, sc.y, sh.y);
        y.z = fmaf(x.z, sc.z, sh.z); y.w = fmaf(x.w, sc.w, sh.w);
        __stcs(&Yv[base + (size_t)k * (4 * DV)], y);
    }
}

// ---------------------------------------------------------------------------
extern "C" void kernel_launch(void* const* d_in, const int* in_sizes, int n_in,
                              void* d_out, int out_size) {
    const float* X     = (const float*)d_in[0];
    const float* gamma = (const float*)d_in[1];
    const float* beta  = (const float*)d_in[2];
    float*       Y     = (float*)d_out;

    // Idempotent, not a stream op — legal under graph capture.
    cudaFuncSetAttribute(bn_fused_kernel,
                         cudaFuncAttributeMaxDynamicSharedMemorySize, SMEM_BYTES);

    bn_init_kernel<<<1, 1>>>();
    bn_fused_kernel<<<GRID, NTH, SMEM_BYTES>>>((const float4*)X, (float4*)Y,
                                               gamma, beta);
}

// round 13
// speedup vs baseline: 1.1357x; 1.1357x over previous
#include <cuda_runtime.h>

// BatchNorm over features: X[N, D], stats over axis 0. N=131072, D=512, fp32.
//
// Round 13 = Round 11 (best: 125.4us) with ONE change: Y stores use
// st.global.wt (write-through, no L2 allocate) instead of __stcs.
// R11 measurement showed phase-2's L2 harvest stuck at ~60MB of a possible
// ~126MB; model: Y write-allocate evicts resident X at ~1:1 during the hit
// window (126/2 = 63MB, matches). Bypassing L2 for Y protects the resident
// set so the LIFO sweep can harvest it all.

#define NROWS  131072
#define DCOLS  512
#define DV     128                  // DCOLS/4 float4 quads per row
#define GRID   296                  // 2 blocks/SM x 148 SMs
#define NTH    512
#define NCH16  (NROWS / 16)         // 8192 16-row chunks

// Scratch (__device__ globals; allocation forbidden).
__device__ float g_psum[DCOLS * GRID];   // [col * GRID + block]
__device__ float g_psq [DCOLS * GRID];
__device__ __align__(16) float g_scale[DCOLS];
__device__ __align__(16) float g_shift[DCOLS];
__device__ unsigned g_bar0;
__device__ unsigned g_bar1;

// Reset barrier state every launch (graph replays need pristine counters).
__global__ void bn_init_kernel() { g_bar0 = 0u; g_bar1 = 0u; }

// Grid-wide barrier: release fence + atomic arrive, acquire-load spin.
// Safe only because all GRID blocks are co-resident (occ 2 x 148 SMs).
__device__ __forceinline__ void grid_barrier(unsigned* ctr, int tid) {
    __syncthreads();
    if (tid == 0) {
        __threadfence();
        atomicAdd(ctr, 1u);
        unsigned v;
        do {
            asm volatile("ld.acquire.gpu.u32 %0, [%1];"
                         : "=r"(v) : "l"(ctr) : "memory");
            if (v >= GRID) break;
            __nanosleep(64);
        } while (true);
    }
    __syncthreads();
}

// Write-through store: no L2 allocation -> does not evict resident X lines.
__device__ __forceinline__ void st_wt(float4* p, float4 v) {
    asm volatile("st.global.wt.v4.f32 [%0], {%1, %2, %3, %4};"
                 :: "l"(p), "f"(v.x), "f"(v.y), "f"(v.z), "f"(v.w)
                 : "memory");
}

__global__ __launch_bounds__(NTH, 2)
void bn_fused_kernel(const float4* __restrict__ Xv, float4* __restrict__ Yv,
                     const float* __restrict__ gamma,
                     const float* __restrict__ beta) {
    const int b   = blockIdx.x;
    const int tid = threadIdx.x;
    const int cq  = tid & 127;   // column quad 0..127
    const int lr  = tid >> 7;    // row lane   0..3

    // Contiguous region: chunks [cs, ce) of 16 rows (27 or 28 chunks).
    const int cs = (int)(((long long)b       * NCH16) / GRID);
    const int ce = (int)(((long long)(b + 1) * NCH16) / GRID);
    const int nIter = (ce - cs) * 4;           // float4-rows per thread
    const size_t base = ((size_t)cs * 16 + (size_t)lr) * DV + (size_t)cq;

    // ---------------- Phase 1: reduce region front-to-back ----------------
    float sx = 0.f, sy = 0.f, sz = 0.f, sw = 0.f;
    float qx = 0.f, qy = 0.f, qz = 0.f, qw = 0.f;

    for (int i = 0; i < nIter; i += 4) {
        float4 x0 = Xv[base + (size_t)(i + 0) * (4 * DV)];
        float4 x1 = Xv[base + (size_t)(i + 1) * (4 * DV)];
        float4 x2 = Xv[base + (size_t)(i + 2) * (4 * DV)];
        float4 x3 = Xv[base + (size_t)(i + 3) * (4 * DV)];

        sx += x0.x; sy += x0.y; sz += x0.z; sw += x0.w;
        qx = fmaf(x0.x, x0.x, qx); qy = fmaf(x0.y, x0.y, qy);
        qz = fmaf(x0.z, x0.z, qz); qw = fmaf(x0.w, x0.w, qw);

        sx += x1.x; sy += x1.y; sz += x1.z; sw += x1.w;
        qx = fmaf(x1.x, x1.x, qx); qy = fmaf(x1.y, x1.y, qy);
        qz = fmaf(x1.z, x1.z, qz); qw = fmaf(x1.w, x1.w, qw);

        sx += x2.x; sy += x2.y; sz += x2.z; sw += x2.w;
        qx = fmaf(x2.x, x2.x, qx); qy = fmaf(x2.y, x2.y, qy);
        qz = fmaf(x2.z, x2.z, qz); qw = fmaf(x2.w, x2.w, qw);

        sx += x3.x; sy += x3.y; sz += x3.z; sw += x3.w;
        qx = fmaf(x3.x, x3.x, qx); qy = fmaf(x3.y, x3.y, qy);
        qz = fmaf(x3.z, x3.z, qz); qw = fmaf(x3.w, x3.w, qw);
    }

    {
        __shared__ float4 shs[NTH];
        __shared__ float4 shq[NTH];
        shs[tid] = make_float4(sx, sy, sz, sw);
        shq[tid] = make_float4(qx, qy, qz, qw);
        __syncthreads();

        if (lr == 0) {
            float4 s = shs[cq];
            float4 q = shq[cq];
            #pragma unroll
            for (int k = 1; k < 4; k++) {
                float4 a  = shs[cq + 128 * k];
                float4 c2 = shq[cq + 128 * k];
                s.x += a.x; s.y += a.y; s.z += a.z; s.w += a.w;
                q.x += c2.x; q.y += c2.y; q.z += c2.z; q.w += c2.w;
            }
            const int col0 = 4 * cq;
            g_psum[(size_t)(col0 + 0) * GRID + b] = s.x;
            g_psum[(size_t)(col0 + 1) * GRID + b] = s.y;
            g_psum[(size_t)(col0 + 2) * GRID + b] = s.z;
            g_psum[(size_t)(col0 + 3) * GRID + b] = s.w;
            g_psq [(size_t)(col0 + 0) * GRID + b] = q.x;
            g_psq [(size_t)(col0 + 1) * GRID + b] = q.y;
            g_psq [(size_t)(col0 + 2) * GRID + b] = q.z;
            g_psq [(size_t)(col0 + 3) * GRID + b] = q.w;
        }
    }

    // ---------------- Barrier 1: all partials visible ----------------
    grid_barrier(&g_bar0, tid);

    // ---------------- Finalize: block b handles columns b, b+GRID ----------
    {
        __shared__ float ss[16];
        __shared__ float sq[16];
        for (int c = b; c < DCOLS; c += GRID) {
            float s = 0.f, q = 0.f;
            if (tid < GRID) {
                s = g_psum[(size_t)c * GRID + tid];
                q = g_psq [(size_t)c * GRID + tid];
            }
            #pragma unroll
            for (int off = 16; off > 0; off >>= 1) {
                s += __shfl_down_sync(0xFFFFFFFFu, s, off);
                q += __shfl_down_sync(0xFFFFFFFFu, q, off);
            }
            const int warp = tid >> 5;
            const int lane = tid & 31;
            if (lane == 0) { ss[warp] = s; sq[warp] = q; }
            __syncthreads();
            if (tid < 16) {
                s = ss[tid];
                q = sq[tid];
                #pragma unroll
                for (int off = 8; off > 0; off >>= 1) {
                    s += __shfl_down_sync(0x0000FFFFu, s, off);
                    q += __shfl_down_sync(0x0000FFFFu, q, off);
                }
                if (tid == 0) {
                    const float inv_n = 1.0f / (float)NROWS;
                    float mean = s * inv_n;
                    float var  = fmaf(-mean, mean, q * inv_n);
                    float inv  = rsqrtf(var);       // no epsilon (matches reference)
                    float scv  = inv * gamma[c];
                    g_scale[c] = scv;
                    g_shift[c] = fmaf(-mean, scv, beta[c]);
                }
            }
            __syncthreads();
        }
    }

    // ---------------- Barrier 2: scale/shift visible ----------------
    grid_barrier(&g_bar1, tid);

    const float4 sc = reinterpret_cast<const float4*>(g_scale)[cq];
    const float4 sh = reinterpret_cast<const float4*>(g_shift)[cq];

    // ---------------- Phase 2: normalize BACK-TO-FRONT ----------------
    // LIFO vs phase-1 read order -> consume resident L2 lines freshest-first.
    // Y stores bypass L2 (write-through) so they don't evict resident X.
    for (int j = nIter - 4; j >= 0; j -= 4) {
        const size_t i0 = base + (size_t)(j + 0) * (4 * DV);
        const size_t i1 = base + (size_t)(j + 1) * (4 * DV);
        const size_t i2 = base + (size_t)(j + 2) * (4 * DV);
        const size_t i3 = base + (size_t)(j + 3) * (4 * DV);
        float4 x0 = Xv[i0];
        float4 x1 = Xv[i1];
        float4 x2 = Xv[i2];
        float4 x3 = Xv[i3];
        float4 y;
        y.x = fmaf(x3.x, sc.x, sh.x); y.y = fmaf(x3.y, sc.y, sh.y);
        y.z = fmaf(x3.z, sc.z, sh.z); y.w = fmaf(x3.w, sc.w, sh.w);
        st_wt(&Yv[i3], y);
        y.x = fmaf(x2.x, sc.x, sh.x); y.y = fmaf(x2.y, sc.y, sh.y);
        y.z = fmaf(x2.z, sc.z, sh.z); y.w = fmaf(x2.w, sc.w, sh.w);
        st_wt(&Yv[i2], y);
        y.x = fmaf(x1.x, sc.x, sh.x); y.y = fmaf(x1.y, sc.y, sh.y);
        y.z = fmaf(x1.z, sc.z, sh.z); y.w = fmaf(x1.w, sc.w, sh.w);
        st_wt(&Yv[i1], y);
        y.x = fmaf(x0.x, sc.x, sh.x); y.y = fmaf(x0.y, sc.y, sh.y);
        y.z = fmaf(x0.z, sc.z, sh.z); y.w = fmaf(x0.w, sc.w, sh.w);
        st_wt(&Yv[i0], y);
    }
}

// ---------------------------------------------------------------------------
extern "C" void kernel_launch(void* const* d_in, const int* in_sizes, int n_in,
                              void* d_out, int out_size) {
    const float* X     = (const float*)d_in[0];
    const float* gamma = (const float*)d_in[1];
    const float* beta  = (const float*)d_in[2];
    float*       Y     = (float*)d_out;

    bn_init_kernel<<<1, 1>>>();
    bn_fused_kernel<<<GRID, NTH>>>((const float4*)X, (float4*)Y, gamma, beta);
}